// round 7
// baseline (speedup 1.0000x reference)
#include <cuda_runtime.h>
#include <stdint.h>

// Problem constants
#define B     1024
#define S     2048
#define R1    20000
#define R2    40000

#define MAIN_THREADS 512
#define NPART 6                    // parts 0-1 = rates_1st, parts 2-5 = rates_2nd
#define RPP   10000                // rates (and real entries) per partition
#define EPT   20                   // entries per thread per partition (pad 10240)
#define PART_PAD (EPT * MAIN_THREADS)   // 10240
#define KPAD  2048u                // pad-entry key (harmless acc slot)
#define SINK  2049                 // redirect target for non-closing stores
#define ACC_SLOTS 2050
#define CHUNK 5                    // EPT / CHUNK = 4 double-buffered stages

// ---------------- static device scratch (no runtime allocation) ----------------
__device__ int       g_counts[NPART][S];
__device__ int       g_cur[NPART][S];
// Key-grouped, transposed entry streams.
//   parts 0-1:  e = ra | k<<11 | rid<<23            (11 + 12 + 14 bits)
//   parts 2-5:  e = ra | rb<<11 | k<<22 | rid<<34   (11 + 11 + 12 + 14 bits)
__device__ uint64_t  g_et[NPART][PART_PAD];

__device__ __forceinline__ int transposeP(int pos) {
    return (pos % EPT) * MAIN_THREADS + pos / EPT;
}

// ---------------- prep kernels ----------------

__global__ void init_counts_kernel() {
    int i = blockIdx.x * blockDim.x + threadIdx.x;
    if (i < NPART * S) (&g_counts[0][0])[i] = 0;
}

__global__ void hist_kernel(const int* __restrict__ inds_1p,
                            const int* __restrict__ inds_2p) {
    int i = blockIdx.x * blockDim.x + threadIdx.x;
    if (i < R1) {
        atomicAdd(&g_counts[i / RPP][inds_1p[i]], 1);
    } else if (i < R1 + R2) {
        int j = i - R1;
        atomicAdd(&g_counts[2 + j / RPP][inds_2p[j]], 1);
    }
}

// One CTA per partition: exclusive scan over its 2048 bins -> running cursors.
__global__ void scan_kernel() {
    __shared__ int buf[2][S];
    const int tid  = threadIdx.x;       // 1024 threads, 2 elems each
    const int part = blockIdx.x;

    const int* cnt = g_counts[part];
    int*       cur = g_cur[part];

    buf[0][tid]        = cnt[tid];
    buf[0][tid + 1024] = cnt[tid + 1024];
    __syncthreads();

    int src = 0;
    for (int off = 1; off < S; off <<= 1) {
        int i0 = tid, i1 = tid + 1024;
        int v0 = buf[src][i0] + (i0 >= off ? buf[src][i0 - off] : 0);
        int v1 = buf[src][i1] + (i1 >= off ? buf[src][i1 - off] : 0);
        __syncthreads();
        buf[1 - src][i0] = v0;
        buf[1 - src][i1] = v1;
        __syncthreads();
        src ^= 1;
    }
    cur[tid]        = (tid == 0) ? 0 : buf[src][tid - 1];
    cur[tid + 1024] = buf[src][tid + 1023];
}

// Scatter entries into key-grouped transposed slots + write pad entries.
__global__ void scatter_pad_kernel(const int* __restrict__ inds_1r,
                                   const int* __restrict__ inds_1p,
                                   const int* __restrict__ inds_2r,
                                   const int* __restrict__ inds_2p) {
    int i = blockIdx.x * blockDim.x + threadIdx.x;
    if (i < R1) {
        int part = i / RPP;
        int rrel = i - part * RPP;
        int p    = inds_1p[i];
        int pos  = atomicAdd(&g_cur[part][p], 1);
        g_et[part][transposeP(pos)] =
              (uint64_t)(uint32_t)inds_1r[i]
            | ((uint64_t)(uint32_t)p    << 11)
            | ((uint64_t)(uint32_t)rrel << 23);
    } else if (i < R1 + R2) {
        int j    = i - R1;
        int part = 2 + j / RPP;
        int rrel = j - (part - 2) * RPP;
        int p    = inds_2p[j];
        int pos  = atomicAdd(&g_cur[part][p], 1);
        g_et[part][transposeP(pos)] =
              (uint64_t)(uint32_t)inds_2r[2 * j]
            | ((uint64_t)(uint32_t)inds_2r[2 * j + 1] << 11)
            | ((uint64_t)(uint32_t)p                  << 22)
            | ((uint64_t)(uint32_t)rrel               << 34);
    } else if (i < R1 + R2 + NPART * (PART_PAD - RPP)) {
        int q    = i - (R1 + R2);
        int part = q / (PART_PAD - RPP);
        int slot = RPP + q % (PART_PAD - RPP);
        uint64_t e = (part < 2) ? ((uint64_t)KPAD << 11) : ((uint64_t)KPAD << 22);
        g_et[part][transposeP(slot)] = e;
    }
}

// ---------------- main kernel ----------------
// TWO batch rows per CTA, fully interleaved in SMEM: every random shared
// access (y, rate, accumulator) is a single LDS.64 serving both rows, and
// the entry stream (LDG + decode) is amortized across rows. 6 partitions of
// 10000 rates staged per CTA. Inner loop branch-free (SEL-redirected run
// close, thread-exclusive interior keys); slice-boundary runs resolved with
// spread SMEM atomics after a barrier.
//
// SMEM: y2(4096) + acc2(4100) + rbuf2(20000) = 28196 floats = 112,784 B
// -> 2 CTAs/SM.

#define SMEM_FLOATS (2 * S + 2 * ACC_SLOTS + 2 * RPP)

template <bool SECOND>
__device__ __forceinline__ void sweep2(
    const uint64_t* __restrict__ ep,      // g_et[part] + tid
    const float* __restrict__ y2,
    const float* __restrict__ rbuf2,
    float* __restrict__ acc2,
    unsigned& firstk, float& f0, float& f1, unsigned& fdone,
    unsigned& lastk, float& l0, float& l1)
{
    uint64_t buf0[CHUNK], buf1[CHUNK];
    #pragma unroll
    for (int u = 0; u < CHUNK; ++u)
        buf0[u] = ep[u * MAIN_THREADS];

    unsigned curk = 0;
    float a0 = 0.f, a1 = 0.f;
    unsigned first_done = 0;
    firstk = SINK; f0 = 0.f; f1 = 0.f;

    #pragma unroll
    for (int c = 0; c < EPT / CHUNK; ++c) {
        uint64_t* cur = (c & 1) ? buf1 : buf0;
        uint64_t* nxt = (c & 1) ? buf0 : buf1;
        if (c + 1 < EPT / CHUNK) {
            const uint64_t* np = ep + (c + 1) * CHUNK * MAIN_THREADS;
            #pragma unroll
            for (int u = 0; u < CHUNK; ++u)
                nxt[u] = np[u * MAIN_THREADS];
        }
        #pragma unroll
        for (int u = 0; u < CHUNK; ++u) {
            uint64_t e = cur[u];
            unsigned k;
            float v0, v1;
            if (SECOND) {
                unsigned ra  = (unsigned)e & 2047u;
                unsigned rb  = ((unsigned)(e >> 11)) & 2047u;
                k            = ((unsigned)(e >> 22)) & 4095u;
                unsigned rid = (unsigned)(e >> 34);
                float2 ya = *(const float2*)(y2 + 2 * ra);
                float2 yb = *(const float2*)(y2 + 2 * rb);
                float2 rr = *(const float2*)(rbuf2 + 2 * rid);
                v0 = ya.x * yb.x * rr.x;
                v1 = ya.y * yb.y * rr.y;
            } else {
                unsigned ra  = (unsigned)e & 2047u;
                k            = ((unsigned)(e >> 11)) & 4095u;
                unsigned rid = (unsigned)(e >> 23);
                float2 ya = *(const float2*)(y2 + 2 * ra);
                float2 rr = *(const float2*)(rbuf2 + 2 * rid);
                v0 = ya.x * rr.x;
                v1 = ya.y * rr.y;
            }
            if (c == 0 && u == 0) {
                curk = k; a0 = v0; a1 = v1;      // prime first run
            } else {
                unsigned same     = (k == curk) ? 1u : 0u;
                unsigned do_store = (1u - same) & first_done;
                float* addr = do_store ? (acc2 + 2 * curk) : (acc2 + 2 * SINK);
                float2 t = *(float2*)addr;        // unconditional LDS.64
                t.x += a0; t.y += a1;
                *(float2*)addr = t;               // unconditional STS.64
                unsigned cap = (1u - same) & (1u - first_done);
                firstk = cap ? curk : firstk;
                f0     = cap ? a0   : f0;
                f1     = cap ? a1   : f1;
                first_done |= (1u - same);
                a0 = same ? (a0 + v0) : v0;
                a1 = same ? (a1 + v1) : v1;
                curk = k;
            }
        }
    }
    fdone = first_done;
    lastk = curk; l0 = a0; l1 = a1;
}

__global__ __launch_bounds__(MAIN_THREADS, 2)
void reaction_main_kernel(const float* __restrict__ y_in,
                          const float* __restrict__ rates_1st,
                          const float* __restrict__ rates_2nd,
                          float* __restrict__ y_out) {
    extern __shared__ float sm[];
    float* y2    = sm;                       // [2*S]     interleaved
    float* acc2  = sm + 2 * S;               // [2*ACC]   interleaved
    float* rbuf2 = sm + 2 * S + 2 * ACC_SLOTS; // [2*RPP] interleaved

    const int b0  = 2 * blockIdx.x;
    const int b1  = b0 + 1;
    const int tid = threadIdx.x;

    // Load two y rows interleaved; zero the accumulator.
    {
        const float4* s0 = (const float4*)(y_in + (size_t)b0 * S);
        const float4* s1 = (const float4*)(y_in + (size_t)b1 * S);
        float4 r0 = s0[tid], r1 = s1[tid];
        float2* d = (float2*)(y2 + 8 * tid);
        d[0] = make_float2(r0.x, r1.x);
        d[1] = make_float2(r0.y, r1.y);
        d[2] = make_float2(r0.z, r1.z);
        d[3] = make_float2(r0.w, r1.w);
        #pragma unroll
        for (int i = tid; i < 2 * ACC_SLOTS; i += MAIN_THREADS)
            acc2[i] = 0.f;
    }

    #pragma unroll 1
    for (int part = 0; part < NPART; ++part) {
        __syncthreads();   // prior sweep's rbuf reads + acc stores done
        {
            const float* base0 = (part < 2)
                ? rates_1st + (size_t)b0 * R1 + part * RPP
                : rates_2nd + (size_t)b0 * R2 + (part - 2) * RPP;
            const float* base1 = (part < 2)
                ? rates_1st + (size_t)b1 * R1 + part * RPP
                : rates_2nd + (size_t)b1 * R2 + (part - 2) * RPP;
            const float4* s0 = (const float4*)base0;
            const float4* s1 = (const float4*)base1;
            for (int i = tid; i < RPP / 4; i += MAIN_THREADS) {
                float4 r0 = __ldcs(s0 + i);
                float4 r1 = __ldcs(s1 + i);
                float2* d = (float2*)(rbuf2 + 8 * i);
                d[0] = make_float2(r0.x, r1.x);
                d[1] = make_float2(r0.y, r1.y);
                d[2] = make_float2(r0.z, r1.z);
                d[3] = make_float2(r0.w, r1.w);
            }
        }
        __syncthreads();

        unsigned firstk, fdone, lastk;
        float f0, f1, l0, l1;
        if (part < 2)
            sweep2<false>(g_et[part] + tid, y2, rbuf2, acc2,
                          firstk, f0, f1, fdone, lastk, l0, l1);
        else
            sweep2<true>(g_et[part] + tid, y2, rbuf2, acc2,
                         firstk, f0, f1, fdone, lastk, l0, l1);

        __syncthreads();   // interior plain stores visible before boundary atomics
        atomicAdd(&acc2[2 * lastk],     l0);
        atomicAdd(&acc2[2 * lastk + 1], l1);
        if (fdone) {
            atomicAdd(&acc2[2 * firstk],     f0);
            atomicAdd(&acc2[2 * firstk + 1], f1);
        }
    }
    __syncthreads();

    // ---- write out both rows (coalesced per row) ----
    #pragma unroll
    for (int i = tid; i < S; i += MAIN_THREADS) {
        float2 t = *(const float2*)(acc2 + 2 * i);
        y_out[(size_t)b0 * S + i] = t.x;
        y_out[(size_t)b1 * S + i] = t.y;
    }
}

// ---------------- launch ----------------

extern "C" void kernel_launch(void* const* d_in, const int* in_sizes, int n_in,
                              void* d_out, int out_size) {
    const float* y_in      = (const float*)d_in[0];
    const float* rates_1st = (const float*)d_in[1];
    const float* rates_2nd = (const float*)d_in[2];
    const int*   inds_1r   = (const int*)d_in[3];
    const int*   inds_1p   = (const int*)d_in[4];
    const int*   inds_2r   = (const int*)d_in[5];
    const int*   inds_2p   = (const int*)d_in[6];
    float*       y_out     = (float*)d_out;

    cudaFuncSetAttribute(reaction_main_kernel,
                         cudaFuncAttributeMaxDynamicSharedMemorySize,
                         SMEM_FLOATS * (int)sizeof(float));

    // Entry-stream build (rebuilt every launch; deterministic)
    init_counts_kernel<<<(NPART * S + 255) / 256, 256>>>();
    hist_kernel<<<(R1 + R2 + 255) / 256, 256>>>(inds_1p, inds_2p);
    scan_kernel<<<NPART, 1024>>>();
    int scat_n = R1 + R2 + NPART * (PART_PAD - RPP);
    scatter_pad_kernel<<<(scat_n + 255) / 256, 256>>>(inds_1r, inds_1p, inds_2r, inds_2p);

    // Main pass: one CTA per TWO batch rows
    reaction_main_kernel<<<B / 2, MAIN_THREADS, SMEM_FLOATS * sizeof(float)>>>(
        y_in, rates_1st, rates_2nd, y_out);
}

// round 8
// speedup vs baseline: 1.3562x; 1.3562x over previous
#include <cuda_runtime.h>
#include <cuda_fp16.h>
#include <stdint.h>

// Problem constants
#define B     1024
#define S     2048
#define R1    20000
#define R2    40000

#define MAIN_THREADS 512
#define NPART 3                    // part0 = rates_1st; part1,2 = rates_2nd halves
#define RPP   20000                // rates (and real entries) per partition
#define EPT   40                   // entries per thread per partition (pad 20480)
#define PART_PAD (EPT * MAIN_THREADS)   // 20480
#define KPAD  2048u                // pad-entry key (harmless acc slot)
#define SINK  2049                 // redirect target for non-closing stores
#define ACC_SLOTS 2050
#define CHUNK 8

// ---------------- static device scratch (no runtime allocation) ----------------
__device__ int       g_counts[NPART][S];
__device__ int       g_cur[NPART][S];
// Key-grouped, transposed entry streams (identical to R6).
//   part0:  e = ra | k<<11 | rid<<23            (11 + 12 + 15 bits)
//   part1+: e = ra | rb<<11 | k<<22 | rid<<34   (11 + 11 + 12 + 15 bits)
__device__ uint64_t  g_et[NPART][PART_PAD];

__device__ __forceinline__ int transposeP(int pos) {
    return (pos % EPT) * MAIN_THREADS + pos / EPT;
}

// ---------------- prep kernels ----------------

__global__ void init_counts_kernel() {
    int i = blockIdx.x * blockDim.x + threadIdx.x;
    if (i < NPART * S) (&g_counts[0][0])[i] = 0;
}

__global__ void hist_kernel(const int* __restrict__ inds_1p,
                            const int* __restrict__ inds_2p) {
    int i = blockIdx.x * blockDim.x + threadIdx.x;
    if (i < R1) {
        atomicAdd(&g_counts[0][inds_1p[i]], 1);
    } else if (i < R1 + R2) {
        int j = i - R1;
        atomicAdd(&g_counts[1 + (j >= RPP)][inds_2p[j]], 1);
    }
}

// One CTA per partition: exclusive scan over its 2048 bins -> running cursors.
__global__ void scan_kernel() {
    __shared__ int buf[2][S];
    const int tid  = threadIdx.x;       // 1024 threads, 2 elems each
    const int part = blockIdx.x;

    const int* cnt = g_counts[part];
    int*       cur = g_cur[part];

    buf[0][tid]        = cnt[tid];
    buf[0][tid + 1024] = cnt[tid + 1024];
    __syncthreads();

    int src = 0;
    for (int off = 1; off < S; off <<= 1) {
        int i0 = tid, i1 = tid + 1024;
        int v0 = buf[src][i0] + (i0 >= off ? buf[src][i0 - off] : 0);
        int v1 = buf[src][i1] + (i1 >= off ? buf[src][i1 - off] : 0);
        __syncthreads();
        buf[1 - src][i0] = v0;
        buf[1 - src][i1] = v1;
        __syncthreads();
        src ^= 1;
    }
    cur[tid]        = (tid == 0) ? 0 : buf[src][tid - 1];
    cur[tid + 1024] = buf[src][tid + 1023];
}

// Scatter entries into key-grouped transposed slots + write pad entries.
__global__ void scatter_pad_kernel(const int* __restrict__ inds_1r,
                                   const int* __restrict__ inds_1p,
                                   const int* __restrict__ inds_2r,
                                   const int* __restrict__ inds_2p) {
    int i = blockIdx.x * blockDim.x + threadIdx.x;
    if (i < R1) {
        int p   = inds_1p[i];
        int pos = atomicAdd(&g_cur[0][p], 1);
        g_et[0][transposeP(pos)] =
              (uint64_t)(uint32_t)inds_1r[i]
            | ((uint64_t)(uint32_t)p << 11)
            | ((uint64_t)(uint32_t)i << 23);
    } else if (i < R1 + R2) {
        int j    = i - R1;
        int part = 1 + (j >= RPP);
        int rrel = j - (part - 1) * RPP;
        int p    = inds_2p[j];
        int pos  = atomicAdd(&g_cur[part][p], 1);
        g_et[part][transposeP(pos)] =
              (uint64_t)(uint32_t)inds_2r[2 * j]
            | ((uint64_t)(uint32_t)inds_2r[2 * j + 1] << 11)
            | ((uint64_t)(uint32_t)p                  << 22)
            | ((uint64_t)(uint32_t)rrel               << 34);
    } else if (i < R1 + R2 + NPART * (PART_PAD - RPP)) {
        int q    = i - (R1 + R2);
        int part = q / (PART_PAD - RPP);
        int slot = RPP + q % (PART_PAD - RPP);
        uint64_t e = (part == 0) ? ((uint64_t)KPAD << 11) : ((uint64_t)KPAD << 22);
        g_et[part][transposeP(slot)] = e;
    }
}

// ---------------- main kernel ----------------
// TWO batch rows per CTA. The random-read tables (y, rates) are packed as
// __half2 {row0, row1}: one 32-bit random LDS serves both rows at the same
// crossbar cost as one fp32 row. Accumulation stays fp32 (float2 SMEM acc,
// register run accumulation). Inner loop branch-free (SEL-redirected run
// close, thread-exclusive interior keys); slice-boundary runs resolved with
// spread SMEM atomics after a barrier. Entry stream LDG + decode amortized
// across the row pair.
//
// SMEM: y2h(2048 h2 = 8KB) + acc2(2*2050 f32 = 16.4KB) + rbuf2h(20000 h2 = 80KB)
//     = 104,592 B -> 2 CTAs/SM.

#define SMEM_BYTES (S * 4 + 2 * ACC_SLOTS * 4 + RPP * 4)

template <bool SECOND>
__device__ __forceinline__ void sweep2(
    const uint64_t* __restrict__ ep,      // g_et[part] + tid
    const __half2* __restrict__ y2h,
    const __half2* __restrict__ rbuf2h,
    float* __restrict__ acc2,
    unsigned& firstk, float& f0, float& f1, unsigned& fdone,
    unsigned& lastk, float& l0, float& l1)
{
    uint64_t buf0[CHUNK], buf1[CHUNK];
    #pragma unroll
    for (int u = 0; u < CHUNK; ++u)
        buf0[u] = ep[u * MAIN_THREADS];

    unsigned curk = 0;
    float a0 = 0.f, a1 = 0.f;
    unsigned first_done = 0;
    firstk = SINK; f0 = 0.f; f1 = 0.f;

    #pragma unroll
    for (int c = 0; c < EPT / CHUNK; ++c) {
        uint64_t* cur = (c & 1) ? buf1 : buf0;
        uint64_t* nxt = (c & 1) ? buf0 : buf1;
        if (c + 1 < EPT / CHUNK) {
            const uint64_t* np = ep + (c + 1) * CHUNK * MAIN_THREADS;
            #pragma unroll
            for (int u = 0; u < CHUNK; ++u)
                nxt[u] = np[u * MAIN_THREADS];
        }
        #pragma unroll
        for (int u = 0; u < CHUNK; ++u) {
            uint64_t e = cur[u];
            unsigned k;
            float v0, v1;
            if (SECOND) {
                unsigned ra  = (unsigned)e & 2047u;
                unsigned rb  = ((unsigned)(e >> 11)) & 2047u;
                k            = ((unsigned)(e >> 22)) & 4095u;
                unsigned rid = (unsigned)(e >> 34);
                float2 fa = __half22float2(y2h[ra]);     // 1 random LDS.32
                float2 fb = __half22float2(y2h[rb]);     // 1 random LDS.32
                float2 fr = __half22float2(rbuf2h[rid]); // 1 random LDS.32
                v0 = fa.x * fb.x * fr.x;
                v1 = fa.y * fb.y * fr.y;
            } else {
                unsigned ra  = (unsigned)e & 2047u;
                k            = ((unsigned)(e >> 11)) & 4095u;
                unsigned rid = (unsigned)(e >> 23);
                float2 fa = __half22float2(y2h[ra]);
                float2 fr = __half22float2(rbuf2h[rid]);
                v0 = fa.x * fr.x;
                v1 = fa.y * fr.y;
            }
            if (c == 0 && u == 0) {
                curk = k; a0 = v0; a1 = v1;      // prime first run
            } else {
                unsigned same     = (k == curk) ? 1u : 0u;
                unsigned do_store = (1u - same) & first_done;
                float* addr = do_store ? (acc2 + 2 * curk) : (acc2 + 2 * SINK);
                float2 t = *(float2*)addr;        // unconditional (mostly broadcast)
                t.x += a0; t.y += a1;
                *(float2*)addr = t;
                unsigned cap = (1u - same) & (1u - first_done);
                firstk = cap ? curk : firstk;
                f0     = cap ? a0   : f0;
                f1     = cap ? a1   : f1;
                first_done |= (1u - same);
                a0 = same ? (a0 + v0) : v0;
                a1 = same ? (a1 + v1) : v1;
                curk = k;
            }
        }
    }
    fdone = first_done;
    lastk = curk; l0 = a0; l1 = a1;
}

__global__ __launch_bounds__(MAIN_THREADS, 2)
void reaction_main_kernel(const float* __restrict__ y_in,
                          const float* __restrict__ rates_1st,
                          const float* __restrict__ rates_2nd,
                          float* __restrict__ y_out) {
    extern __shared__ char smraw[];
    __half2* y2h    = (__half2*)smraw;                       // [S]
    float*   acc2   = (float*)(smraw + S * 4);               // [2*ACC_SLOTS]
    __half2* rbuf2h = (__half2*)(smraw + S * 4 + 2 * ACC_SLOTS * 4); // [RPP]

    const int b0  = 2 * blockIdx.x;
    const int b1  = b0 + 1;
    const int tid = threadIdx.x;

    // Load two y rows -> packed half2; zero the accumulator.
    {
        const float4* s0 = (const float4*)(y_in + (size_t)b0 * S);
        const float4* s1 = (const float4*)(y_in + (size_t)b1 * S);
        float4 r0 = s0[tid], r1 = s1[tid];
        __half2* d = y2h + 4 * tid;
        d[0] = __floats2half2_rn(r0.x, r1.x);
        d[1] = __floats2half2_rn(r0.y, r1.y);
        d[2] = __floats2half2_rn(r0.z, r1.z);
        d[3] = __floats2half2_rn(r0.w, r1.w);
        #pragma unroll
        for (int i = tid; i < 2 * ACC_SLOTS; i += MAIN_THREADS)
            acc2[i] = 0.f;
    }

    #pragma unroll 1
    for (int part = 0; part < NPART; ++part) {
        __syncthreads();   // prior sweep's rbuf reads + acc stores done
        {
            const float* base0 = (part == 0)
                ? rates_1st + (size_t)b0 * R1
                : rates_2nd + (size_t)b0 * R2 + (part - 1) * RPP;
            const float* base1 = (part == 0)
                ? rates_1st + (size_t)b1 * R1
                : rates_2nd + (size_t)b1 * R2 + (part - 1) * RPP;
            const float4* s0 = (const float4*)base0;
            const float4* s1 = (const float4*)base1;
            for (int i = tid; i < RPP / 4; i += MAIN_THREADS) {
                float4 r0 = __ldcs(s0 + i);
                float4 r1 = __ldcs(s1 + i);
                __half2* d = rbuf2h + 4 * i;
                d[0] = __floats2half2_rn(r0.x, r1.x);
                d[1] = __floats2half2_rn(r0.y, r1.y);
                d[2] = __floats2half2_rn(r0.z, r1.z);
                d[3] = __floats2half2_rn(r0.w, r1.w);
            }
        }
        __syncthreads();

        unsigned firstk, fdone, lastk;
        float f0, f1, l0, l1;
        if (part == 0)
            sweep2<false>(g_et[0] + tid, y2h, rbuf2h, acc2,
                          firstk, f0, f1, fdone, lastk, l0, l1);
        else if (part == 1)
            sweep2<true>(g_et[1] + tid, y2h, rbuf2h, acc2,
                         firstk, f0, f1, fdone, lastk, l0, l1);
        else
            sweep2<true>(g_et[2] + tid, y2h, rbuf2h, acc2,
                         firstk, f0, f1, fdone, lastk, l0, l1);

        __syncthreads();   // interior plain stores visible before boundary atomics
        atomicAdd(&acc2[2 * lastk],     l0);
        atomicAdd(&acc2[2 * lastk + 1], l1);
        if (fdone) {
            atomicAdd(&acc2[2 * firstk],     f0);
            atomicAdd(&acc2[2 * firstk + 1], f1);
        }
    }
    __syncthreads();

    // ---- write out both rows ----
    #pragma unroll
    for (int i = tid; i < S; i += MAIN_THREADS) {
        float2 t = *(const float2*)(acc2 + 2 * i);
        y_out[(size_t)b0 * S + i] = t.x;
        y_out[(size_t)b1 * S + i] = t.y;
    }
}

// ---------------- launch ----------------

extern "C" void kernel_launch(void* const* d_in, const int* in_sizes, int n_in,
                              void* d_out, int out_size) {
    const float* y_in      = (const float*)d_in[0];
    const float* rates_1st = (const float*)d_in[1];
    const float* rates_2nd = (const float*)d_in[2];
    const int*   inds_1r   = (const int*)d_in[3];
    const int*   inds_1p   = (const int*)d_in[4];
    const int*   inds_2r   = (const int*)d_in[5];
    const int*   inds_2p   = (const int*)d_in[6];
    float*       y_out     = (float*)d_out;

    cudaFuncSetAttribute(reaction_main_kernel,
                         cudaFuncAttributeMaxDynamicSharedMemorySize,
                         SMEM_BYTES);

    // Entry-stream build (rebuilt every launch; deterministic)
    init_counts_kernel<<<(NPART * S + 255) / 256, 256>>>();
    hist_kernel<<<(R1 + R2 + 255) / 256, 256>>>(inds_1p, inds_2p);
    scan_kernel<<<NPART, 1024>>>();
    int scat_n = R1 + R2 + NPART * (PART_PAD - RPP);
    scatter_pad_kernel<<<(scat_n + 255) / 256, 256>>>(inds_1r, inds_1p, inds_2r, inds_2p);

    // Main pass: one CTA per TWO batch rows
    reaction_main_kernel<<<B / 2, MAIN_THREADS, SMEM_BYTES>>>(
        y_in, rates_1st, rates_2nd, y_out);
}